// round 7
// baseline (speedup 1.0000x reference)
#include <cuda_runtime.h>
#include <math.h>

#define BATCH 8
#define HH 720
#define WW 1280
#define HW (HH * WW)
#define NPIX (BATCH * HW)

// Packed accumulator: (cnt, ox, oy, pad). 16B aligned for red.global.add.v4.f32.
// Invariant: all-zero at every kernel_launch entry. BSS zero-init covers the
// first call; normalize_kernel restores the invariant on every call. This
// removes the dedicated zero kernel entirely.
__device__ float4 g_acc[NPIX];

// ---------------------------------------------------------------------------
// Kernel 1: scatter. One thread per source pixel; 4 vector reductions
// (one per bilinear corner). Inputs read with evict-first (.cs) hints.
// ---------------------------------------------------------------------------
__device__ __forceinline__ void red_add_v4(float4* addr, float a, float b, float c) {
    asm volatile(
        "red.global.add.v4.f32 [%0], {%1, %2, %3, %4};"
        :: "l"(addr), "f"(a), "f"(b), "f"(c), "f"(0.0f)
        : "memory");
}

__global__ void scatter_kernel(const float* __restrict__ flow,
                               const float* __restrict__ depth) {
    int i = blockIdx.x * blockDim.x + threadIdx.x;
    if (i >= NPIX) return;

    int b = i / HW;
    int p = i - b * HW;
    int y = p / WW;
    int x = p - y * WW;

    const float* fbase = flow + (size_t)b * 2 * HW;
    float fx = __ldcs(fbase + p);
    float fy = __ldcs(fbase + HW + p);
    float d  = __ldcs(depth + i);

    float x2 = (float)x + fx;
    float y2 = (float)y + fy;

    if (!(x2 >= 0.f && x2 <= (float)(WW - 1) &&
          y2 >= 0.f && y2 <= (float)(HH - 1)))
        return;

    int xL = (int)floorf(x2);
    int yT = (int)floorf(y2);
    int xR = min(xL + 1, WW - 1);
    int yB = min(yT + 1, HH - 1);

    float wx = -fx * d;
    float wy = -fy * d;

    int base = b * HW;
    int rT = base + yT * WW;
    int rB = base + yB * WW;

    red_add_v4(&g_acc[rT + xL], d, wx, wy);
    red_add_v4(&g_acc[rT + xR], d, wx, wy);
    red_add_v4(&g_acc[rB + xL], d, wx, wy);
    red_add_v4(&g_acc[rB + xR], d, wx, wy);
}

// ---------------------------------------------------------------------------
// Kernel 2: normalize + write (B, 2, H, W), and restore the all-zero
// invariant on g_acc (stores hit L2-dirty lines just read — no DRAM fill).
// 4 independent pixels per thread (coalesced strided) for MLP.
// ---------------------------------------------------------------------------
__global__ void normalize_kernel(float* __restrict__ out) {
    const float4 z = make_float4(0.f, 0.f, 0.f, 0.f);
    int tid = blockIdx.x * blockDim.x + threadIdx.x;
    int stride = gridDim.x * blockDim.x;          // = NPIX/4 exactly

    int idx[4];
    float4 a[4];
#pragma unroll
    for (int j = 0; j < 4; j++) {
        idx[j] = tid + j * stride;
        a[j] = g_acc[idx[j]];                     // 4 loads in flight
    }
#pragma unroll
    for (int j = 0; j < 4; j++) {
        g_acc[idx[j]] = z;                        // restore invariant

        float ox = 0.f, oy = 0.f;
        if (a[j].x > 0.f) {
            float inv = 1.f / a[j].x;
            ox = a[j].y * inv;
            oy = a[j].z * inv;
        }
        int b = idx[j] / HW;
        int p = idx[j] - b * HW;
        float* obase = out + (size_t)b * 2 * HW;
        __stcs(obase + p,      ox);
        __stcs(obase + HW + p, oy);
    }
}

extern "C" void kernel_launch(void* const* d_in, const int* in_sizes, int n_in,
                              void* d_out, int out_size) {
    const float* flow  = (const float*)d_in[0];   // (B, 2, H, W)
    const float* depth = (const float*)d_in[1];   // (B, 1, H, W)
    float* out = (float*)d_out;                   // (B, 2, H, W)

    (void)in_sizes; (void)n_in; (void)out_size;

    const int threads = 256;

    int blocks = (NPIX + threads - 1) / threads;  // 28800
    scatter_kernel<<<blocks, threads>>>(flow, depth);

    int nblocks = (NPIX / 4) / threads;           // 7200
    normalize_kernel<<<nblocks, threads>>>(out);
}

// round 8
// speedup vs baseline: 1.3310x; 1.3310x over previous
#include <cuda_runtime.h>
#include <math.h>

#define BATCH 8
#define HH 720
#define WW 1280
#define HW (HH * WW)
#define NPIX (BATCH * HW)

#define CB 2                       // batches per chunk
#define NCHUNK (BATCH / CB)        // 4
#define CHUNK_PIX (CB * HW)        // 1,843,200

#define THREADS 256
#define SBLK (CHUNK_PIX / THREADS)       // 7200 scatter blocks / chunk (1 px/thr)
#define ZBLK (CHUNK_PIX / (2 * THREADS)) // 3600 zero blocks / chunk (2 f4/thr)
#define NBLK (CHUNK_PIX / (2 * THREADS)) // 3600 norm blocks / chunk (2 px/thr)

// Full packed accumulator: (cnt, ox, oy, pad) per pixel.
__device__ float4 g_acc[NPIX];

__device__ __forceinline__ void red_add_v4(float4* addr, float a, float b, float c) {
    asm volatile(
        "red.global.add.v4.f32 [%0], {%1, %2, %3, %4};"
        :: "l"(addr), "f"(a), "f"(b), "f"(c), "f"(0.0f)
        : "memory");
}

// ---------------------------------------------------------------------------
// Role bodies (per-chunk).
// ---------------------------------------------------------------------------
__device__ __forceinline__ void do_scatter(int blk, int chunk,
                                           const float* __restrict__ flow,
                                           const float* __restrict__ depth) {
    int li = blk * THREADS + threadIdx.x;            // [0, CHUNK_PIX)
    int gi = chunk * CHUNK_PIX + li;                 // global pixel

    int b = gi / HW;
    int p = gi - b * HW;
    int y = p / WW;
    int x = p - y * WW;

    const float* fbase = flow + (size_t)b * 2 * HW;
    float fx = __ldcs(fbase + p);
    float fy = __ldcs(fbase + HW + p);
    float d  = __ldcs(depth + gi);

    float x2 = (float)x + fx;
    float y2 = (float)y + fy;

    if (!(x2 >= 0.f && x2 <= (float)(WW - 1) &&
          y2 >= 0.f && y2 <= (float)(HH - 1)))
        return;

    int xL = (int)floorf(x2);
    int yT = (int)floorf(y2);
    int xR = min(xL + 1, WW - 1);
    int yB = min(yT + 1, HH - 1);

    float wx = -fx * d;
    float wy = -fy * d;

    int base = b * HW;
    int rT = base + yT * WW;
    int rB = base + yB * WW;

    red_add_v4(&g_acc[rT + xL], d, wx, wy);
    red_add_v4(&g_acc[rT + xR], d, wx, wy);
    red_add_v4(&g_acc[rB + xL], d, wx, wy);
    red_add_v4(&g_acc[rB + xR], d, wx, wy);
}

__device__ __forceinline__ void do_zero(int blk, int chunk) {
    int t = blk * THREADS + threadIdx.x;             // [0, CHUNK_PIX/2)
    float4 z = make_float4(0.f, 0.f, 0.f, 0.f);
    int base = chunk * CHUNK_PIX;
    g_acc[base + t] = z;
    g_acc[base + t + CHUNK_PIX / 2] = z;
}

__device__ __forceinline__ void do_norm(int blk, int chunk,
                                        float* __restrict__ out) {
    int t = blk * THREADS + threadIdx.x;             // [0, CHUNK_PIX/2)
    int i0 = chunk * CHUNK_PIX + t;
    int i1 = i0 + CHUNK_PIX / 2;

    float4 a0 = g_acc[i0];
    float4 a1 = g_acc[i1];

    float ox0 = 0.f, oy0 = 0.f;
    if (a0.x > 0.f) { float inv = 1.f / a0.x; ox0 = a0.y * inv; oy0 = a0.z * inv; }
    float ox1 = 0.f, oy1 = 0.f;
    if (a1.x > 0.f) { float inv = 1.f / a1.x; ox1 = a1.y * inv; oy1 = a1.z * inv; }

    int b0 = i0 / HW, p0 = i0 - b0 * HW;
    int b1 = i1 / HW, p1 = i1 - b1 * HW;

    float* ob0 = out + (size_t)b0 * 2 * HW;
    float* ob1 = out + (size_t)b1 * 2 * HW;
    __stcs(ob0 + p0,      ox0);
    __stcs(ob0 + HW + p0, oy0);
    __stcs(ob1 + p1,      ox1);
    __stcs(ob1 + HW + p1, oy1);
}

// ---------------------------------------------------------------------------
// Fused pipeline kernel: blockIdx.x is partitioned into
// [scatter(cS) | zero(cZ) | norm(cN)] role ranges. Roles touch disjoint
// accumulator chunks; ordering across chunks is enforced by kernel boundaries.
// ---------------------------------------------------------------------------
__global__ void pipe_kernel(const float* __restrict__ flow,
                            const float* __restrict__ depth,
                            float* __restrict__ out,
                            int nS, int cS, int nZ, int cZ, int nN, int cN) {
    int blk = blockIdx.x;
    if (blk < nS) {
        do_scatter(blk, cS, flow, depth);
    } else if (blk < nS + nZ) {
        do_zero(blk - nS, cZ);
    } else {
        do_norm(blk - nS - nZ, cN, out);
    }
}

extern "C" void kernel_launch(void* const* d_in, const int* in_sizes, int n_in,
                              void* d_out, int out_size) {
    const float* flow  = (const float*)d_in[0];   // (B, 2, H, W)
    const float* depth = (const float*)d_in[1];   // (B, 1, H, W)
    float* out = (float*)d_out;                   // (B, 2, H, W)

    (void)in_sizes; (void)n_in; (void)out_size;

    // Pipeline: Z0 | S0+Z1 | S1+Z2+N0 | S2+Z3+N1 | S3+N2 | N3
    pipe_kernel<<<ZBLK, THREADS>>>(flow, depth, out,
                                   0, 0, ZBLK, 0, 0, 0);
    pipe_kernel<<<SBLK + ZBLK, THREADS>>>(flow, depth, out,
                                   SBLK, 0, ZBLK, 1, 0, 0);
    pipe_kernel<<<SBLK + ZBLK + NBLK, THREADS>>>(flow, depth, out,
                                   SBLK, 1, ZBLK, 2, NBLK, 0);
    pipe_kernel<<<SBLK + ZBLK + NBLK, THREADS>>>(flow, depth, out,
                                   SBLK, 2, ZBLK, 3, NBLK, 1);
    pipe_kernel<<<SBLK + NBLK, THREADS>>>(flow, depth, out,
                                   SBLK, 3, 0, 0, NBLK, 2);
    pipe_kernel<<<NBLK, THREADS>>>(flow, depth, out,
                                   0, 0, 0, 0, NBLK, 3);
}

// round 9
// speedup vs baseline: 1.3552x; 1.0181x over previous
#include <cuda_runtime.h>
#include <math.h>

#define BATCH 8
#define HH 720
#define WW 1280
#define HW (HH * WW)
#define NPIX (BATCH * HW)

#define CB 2                       // batches per chunk
#define NCHUNK (BATCH / CB)        // 4
#define CHUNK_PIX (CB * HW)        // 1,843,200

#define THREADS 256
#define SBLK (CHUNK_PIX / THREADS)       // 7200 scatter blocks / chunk
#define ZBLK (CHUNK_PIX / (2 * THREADS)) // 3600 zero blocks / chunk
#define NBLK (CHUNK_PIX / (2 * THREADS)) // 3600 norm blocks / chunk

// Full packed accumulator: (cnt, ox, oy, pad) per pixel.
__device__ float4 g_acc[NPIX];

__device__ __forceinline__ void red_add_v4(float4* addr, float a, float b, float c) {
    asm volatile(
        "red.global.add.v4.f32 [%0], {%1, %2, %3, %4};"
        :: "l"(addr), "f"(a), "f"(b), "f"(c), "f"(0.0f)
        : "memory");
}

// ---------------------------------------------------------------------------
// Role bodies (per-chunk). blk is the role-local block index.
// ---------------------------------------------------------------------------
__device__ __forceinline__ void do_scatter(int blk, int chunk,
                                           const float* __restrict__ flow,
                                           const float* __restrict__ depth) {
    int li = blk * THREADS + threadIdx.x;            // [0, CHUNK_PIX)
    int gi = chunk * CHUNK_PIX + li;                 // global pixel

    int b = gi / HW;
    int p = gi - b * HW;
    int y = p / WW;
    int x = p - y * WW;

    const float* fbase = flow + (size_t)b * 2 * HW;
    float fx = __ldcs(fbase + p);
    float fy = __ldcs(fbase + HW + p);
    float d  = __ldcs(depth + gi);

    float x2 = (float)x + fx;
    float y2 = (float)y + fy;

    if (!(x2 >= 0.f && x2 <= (float)(WW - 1) &&
          y2 >= 0.f && y2 <= (float)(HH - 1)))
        return;

    int xL = (int)floorf(x2);
    int yT = (int)floorf(y2);
    int xR = min(xL + 1, WW - 1);
    int yB = min(yT + 1, HH - 1);

    float wx = -fx * d;
    float wy = -fy * d;

    int base = b * HW;
    int rT = base + yT * WW;
    int rB = base + yB * WW;

    red_add_v4(&g_acc[rT + xL], d, wx, wy);
    red_add_v4(&g_acc[rT + xR], d, wx, wy);
    red_add_v4(&g_acc[rB + xL], d, wx, wy);
    red_add_v4(&g_acc[rB + xR], d, wx, wy);
}

__device__ __forceinline__ void do_zero(int blk, int chunk) {
    int t = blk * THREADS + threadIdx.x;             // [0, CHUNK_PIX/2)
    float4 z = make_float4(0.f, 0.f, 0.f, 0.f);
    int base = chunk * CHUNK_PIX;
    g_acc[base + t] = z;
    g_acc[base + t + CHUNK_PIX / 2] = z;
}

__device__ __forceinline__ void do_norm(int blk, int chunk,
                                        float* __restrict__ out) {
    int t = blk * THREADS + threadIdx.x;             // [0, CHUNK_PIX/2)
    int i0 = chunk * CHUNK_PIX + t;
    int i1 = i0 + CHUNK_PIX / 2;

    float4 a0 = g_acc[i0];
    float4 a1 = g_acc[i1];

    float ox0 = 0.f, oy0 = 0.f;
    if (a0.x > 0.f) { float inv = 1.f / a0.x; ox0 = a0.y * inv; oy0 = a0.z * inv; }
    float ox1 = 0.f, oy1 = 0.f;
    if (a1.x > 0.f) { float inv = 1.f / a1.x; ox1 = a1.y * inv; oy1 = a1.z * inv; }

    int b0 = i0 / HW, p0 = i0 - b0 * HW;
    int b1 = i1 / HW, p1 = i1 - b1 * HW;

    float* ob0 = out + (size_t)b0 * 2 * HW;
    float* ob1 = out + (size_t)b1 * 2 * HW;
    __stcs(ob0 + p0,      ox0);
    __stcs(ob0 + HW + p0, oy0);
    __stcs(ob1 + p1,      ox1);
    __stcs(ob1 + HW + p1, oy1);
}

// ---------------------------------------------------------------------------
// Striped fused kernels: roles interleaved across blockIdx so every
// scheduling wave carries a mix of REDG-bound (scatter) and DRAM-bound
// (zero/norm) blocks. Ordering across chunks enforced by kernel boundaries.
// ---------------------------------------------------------------------------
// mode 0: Z only.  mode 1: S+Z (stripe 3: 2S,1Z).
// mode 2: S+Z+N (stripe 4: 2S,1Z,1N).  mode 3: S+N (stripe 3: 2S,1N).
// mode 4: N only.
__global__ void pipe_kernel(const float* __restrict__ flow,
                            const float* __restrict__ depth,
                            float* __restrict__ out,
                            int mode, int cS, int cZ, int cN) {
    int blk = blockIdx.x;
    if (mode == 0) {
        do_zero(blk, cZ);
    } else if (mode == 1) {
        int g = blk / 3, r = blk - g * 3;
        if (r < 2) do_scatter(g * 2 + r, cS, flow, depth);
        else       do_zero(g, cZ);
    } else if (mode == 2) {
        int g = blk >> 2, r = blk & 3;
        if (r < 2)       do_scatter(g * 2 + r, cS, flow, depth);
        else if (r == 2) do_zero(g, cZ);
        else             do_norm(g, cN, out);
    } else if (mode == 3) {
        int g = blk / 3, r = blk - g * 3;
        if (r < 2) do_scatter(g * 2 + r, cS, flow, depth);
        else       do_norm(g, cN, out);
    } else {
        do_norm(blk, cN, out);
    }
}

extern "C" void kernel_launch(void* const* d_in, const int* in_sizes, int n_in,
                              void* d_out, int out_size) {
    const float* flow  = (const float*)d_in[0];   // (B, 2, H, W)
    const float* depth = (const float*)d_in[1];   // (B, 1, H, W)
    float* out = (float*)d_out;                   // (B, 2, H, W)

    (void)in_sizes; (void)n_in; (void)out_size;

    // Pipeline: Z0 | S0+Z1 | S1+Z2+N0 | S2+Z3+N1 | S3+N2 | N3
    pipe_kernel<<<ZBLK, THREADS>>>(flow, depth, out, 0, 0, 0, 0);
    pipe_kernel<<<SBLK + ZBLK, THREADS>>>(flow, depth, out, 1, 0, 1, 0);
    pipe_kernel<<<SBLK + ZBLK + NBLK, THREADS>>>(flow, depth, out, 2, 1, 2, 0);
    pipe_kernel<<<SBLK + ZBLK + NBLK, THREADS>>>(flow, depth, out, 2, 2, 3, 1);
    pipe_kernel<<<SBLK + NBLK, THREADS>>>(flow, depth, out, 3, 3, 0, 2);
    pipe_kernel<<<NBLK, THREADS>>>(flow, depth, out, 4, 0, 0, 3);
}